// round 2
// baseline (speedup 1.0000x reference)
#include <cuda_runtime.h>
#include <cstdint>

#define N_NODES 100000
#define N_EDGES 1600000
#define IN_F    512
#define OUT_F   128

// ---------------- scratch (static device allocations; no cudaMalloc) --------
__device__ int   g_deg_src[N_NODES];
__device__ int   g_deg_dst[N_NODES];
__device__ float g_h[(size_t)N_NODES * OUT_F];   // projected features, 51.2 MB

// ---------------- helpers ---------------------------------------------------
union F2U { unsigned long long u; float2 f; };

__device__ __forceinline__ unsigned long long ffma2(unsigned long long a,
                                                    unsigned long long b,
                                                    unsigned long long c) {
    unsigned long long d;
    asm("fma.rn.f32x2 %0, %1, %2, %3;" : "=l"(d) : "l"(a), "l"(b), "l"(c));
    return d;
}

__device__ __forceinline__ float f2_comp(unsigned long long u, int p) {
    F2U t; t.u = u;
    return p ? t.f.y : t.f.x;
}

// ---------------- kernel 1: zero degree arrays ------------------------------
__global__ void zero_deg_kernel() {
    int i = blockIdx.x * blockDim.x + threadIdx.x;
    if (i < N_NODES) { g_deg_src[i] = 0; g_deg_dst[i] = 0; }
}

// ---------------- kernel 2: degrees from edge list --------------------------
__global__ void degree_kernel(const int* __restrict__ src,
                              const int* __restrict__ dst) {
    int e = blockIdx.x * blockDim.x + threadIdx.x;
    if (e < N_EDGES) {
        atomicAdd(&g_deg_src[__ldg(&src[e])], 1);
        atomicAdd(&g_deg_dst[__ldg(&dst[e])], 1);
    }
}

// ---------------- kernel 3: GEMM  h = (feat @ W) * rsqrt(max(out_deg,1)) ----
// BM=128 rows, BN=128 (=OUT_F) cols, BK=16, 256 threads.
// Each thread: 8 rows (as 4 f32x2 row-pairs) x 8 cols (2 groups of 4 cols:
// tx*4 .. +3 and 64+tx*4 .. +3, for conflict-free LDS).
// B is stored value-duplicated in smem so packed f32x2 FMA needs no per-k packs.
__global__ __launch_bounds__(256) void gemm_kernel(const float* __restrict__ feat,
                                                   const float* __restrict__ W) {
    __shared__ float As[16][128];   // [k][m]  (transposed)
    __shared__ float Bs[16][256];   // [k][2*n] duplicated: Bs[k][2c]=Bs[k][2c+1]=W[k][c]

    const int tid = threadIdx.x;
    const int m0  = blockIdx.x * 128;
    const int tx  = tid & 15;          // 16 col-groups
    const int ty  = tid >> 4;          // 16 row-groups of 8 rows

    unsigned long long acc[4][8];
    #pragma unroll
    for (int i = 0; i < 4; i++)
        #pragma unroll
        for (int j = 0; j < 8; j++) acc[i][j] = 0ULL;   // (0.f,0.f)

    float4 pa[2], pb[2];

    // prefetch tile 0
    #pragma unroll
    for (int i = 0; i < 2; i++) {
        int id   = tid * 2 + i;
        int arow = id >> 2, kc = (id & 3) * 4;
        int grow = m0 + arow;
        pa[i] = (grow < N_NODES)
              ? *(const float4*)&feat[(size_t)grow * IN_F + kc]
              : make_float4(0.f, 0.f, 0.f, 0.f);
        int brow = id >> 5, col = (id & 31) * 4;
        pb[i] = *(const float4*)&W[(size_t)brow * OUT_F + col];
    }

    for (int t = 0; t < IN_F / 16; t++) {
        // store prefetched tile to smem
        #pragma unroll
        for (int i = 0; i < 2; i++) {
            int id   = tid * 2 + i;
            int arow = id >> 2, kc = (id & 3) * 4;
            As[kc + 0][arow] = pa[i].x;
            As[kc + 1][arow] = pa[i].y;
            As[kc + 2][arow] = pa[i].z;
            As[kc + 3][arow] = pa[i].w;
            int brow = id >> 5, col = (id & 31) * 4;
            float4 v = pb[i];
            Bs[brow][2*col + 0] = v.x; Bs[brow][2*col + 1] = v.x;
            Bs[brow][2*col + 2] = v.y; Bs[brow][2*col + 3] = v.y;
            Bs[brow][2*col + 4] = v.z; Bs[brow][2*col + 5] = v.z;
            Bs[brow][2*col + 6] = v.w; Bs[brow][2*col + 7] = v.w;
        }
        __syncthreads();

        // prefetch next tile while computing this one
        if (t + 1 < IN_F / 16) {
            int k0 = (t + 1) * 16;
            #pragma unroll
            for (int i = 0; i < 2; i++) {
                int id   = tid * 2 + i;
                int arow = id >> 2, kc = (id & 3) * 4;
                int grow = m0 + arow;
                pa[i] = (grow < N_NODES)
                      ? *(const float4*)&feat[(size_t)grow * IN_F + k0 + kc]
                      : make_float4(0.f, 0.f, 0.f, 0.f);
                int brow = id >> 5, col = (id & 31) * 4;
                pb[i] = *(const float4*)&W[(size_t)(k0 + brow) * OUT_F + col];
            }
        }

        #pragma unroll
        for (int k = 0; k < 16; k++) {
            // A: 8 rows = 4 packed row-pairs (broadcast within warp: 2 distinct lines)
            ulonglong2 a01 = *(const ulonglong2*)&As[k][ty * 8];
            ulonglong2 a23 = *(const ulonglong2*)&As[k][ty * 8 + 4];
            unsigned long long am[4] = { a01.x, a01.y, a23.x, a23.y };
            // B: cols tx*4..+3 (dup floats at Bs[k][tx*8..+7]) and 64+tx*4..+3
            ulonglong2 bA = *(const ulonglong2*)&Bs[k][tx * 8];
            ulonglong2 bB = *(const ulonglong2*)&Bs[k][tx * 8 + 4];
            ulonglong2 bC = *(const ulonglong2*)&Bs[k][128 + tx * 8];
            ulonglong2 bD = *(const ulonglong2*)&Bs[k][128 + tx * 8 + 4];
            unsigned long long bn[8] = { bA.x, bA.y, bB.x, bB.y,
                                         bC.x, bC.y, bD.x, bD.y };
            #pragma unroll
            for (int mp = 0; mp < 4; mp++)
                #pragma unroll
                for (int n = 0; n < 8; n++)
                    acc[mp][n] = ffma2(am[mp], bn[n], acc[mp][n]);
        }
        __syncthreads();
    }

    // epilogue: scale rows by rsqrt(max(out_deg,1)) and store to g_h
    #pragma unroll
    for (int mp = 0; mp < 4; mp++) {
        int rbase = m0 + ty * 8 + 2 * mp;
        #pragma unroll
        for (int p = 0; p < 2; p++) {
            int r = rbase + p;
            if (r < N_NODES) {
                float s = rsqrtf(fmaxf((float)g_deg_src[r], 1.0f));
                float4 v0, v1;
                v0.x = f2_comp(acc[mp][0], p) * s;
                v0.y = f2_comp(acc[mp][1], p) * s;
                v0.z = f2_comp(acc[mp][2], p) * s;
                v0.w = f2_comp(acc[mp][3], p) * s;
                v1.x = f2_comp(acc[mp][4], p) * s;
                v1.y = f2_comp(acc[mp][5], p) * s;
                v1.z = f2_comp(acc[mp][6], p) * s;
                v1.w = f2_comp(acc[mp][7], p) * s;
                *(float4*)&g_h[(size_t)r * OUT_F + tx * 4]      = v0;
                *(float4*)&g_h[(size_t)r * OUT_F + 64 + tx * 4] = v1;
            }
        }
    }
}

// ---------------- kernel 4: edge scatter with vector red --------------------
// 32 threads per edge; each thread handles 4 consecutive output floats.
__global__ __launch_bounds__(256) void scatter_kernel(const int*   __restrict__ src,
                                                      const int*   __restrict__ dst,
                                                      const float* __restrict__ ew,
                                                      float*       __restrict__ out) {
    long long gtid = (long long)blockIdx.x * blockDim.x + threadIdx.x;
    int eid  = (int)(gtid >> 5);
    if (eid >= N_EDGES) return;
    int lane = (int)(gtid & 31);
    int col  = lane * 4;

    int   s = __ldg(&src[eid]);
    int   d = __ldg(&dst[eid]);
    float w = __ldg(&ew[eid]);

    float4 v = *(const float4*)&g_h[(size_t)s * OUT_F + col];
    v.x *= w; v.y *= w; v.z *= w; v.w *= w;

    float* p = &out[(size_t)d * OUT_F + col];
    asm volatile("red.global.add.v4.f32 [%0], {%1, %2, %3, %4};"
                 :: "l"(p), "f"(v.x), "f"(v.y), "f"(v.z), "f"(v.w)
                 : "memory");
}

// ---------------- kernel 5: finalize  out = out*rsqrt(in_deg) + bias --------
__global__ __launch_bounds__(256) void finalize_kernel(float* __restrict__ out,
                                                       const float* __restrict__ bias) {
    int i = blockIdx.x * blockDim.x + threadIdx.x;      // float4 index
    if (i >= N_NODES * (OUT_F / 4)) return;
    int n = i / (OUT_F / 4);
    int c = (i % (OUT_F / 4)) * 4;

    float  s = rsqrtf(fmaxf((float)g_deg_dst[n], 1.0f));
    float4 b = *(const float4*)&bias[c];
    float4 v = *(const float4*)&out[(size_t)n * OUT_F + c];
    v.x = v.x * s + b.x;
    v.y = v.y * s + b.y;
    v.z = v.z * s + b.z;
    v.w = v.w * s + b.w;
    *(float4*)&out[(size_t)n * OUT_F + c] = v;
}

// ---------------- launch ----------------------------------------------------
extern "C" void kernel_launch(void* const* d_in, const int* in_sizes, int n_in,
                              void* d_out, int out_size) {
    const float* feat   = (const float*)d_in[0];
    const float* weight = (const float*)d_in[1];
    const float* bias   = (const float*)d_in[2];
    const float* ew     = (const float*)d_in[3];
    const int*   src    = (const int*)d_in[4];
    const int*   dst    = (const int*)d_in[5];
    float*       out    = (float*)d_out;

    (void)in_sizes; (void)n_in; (void)out_size;

    zero_deg_kernel<<<(N_NODES + 255) / 256, 256>>>();
    cudaMemsetAsync(out, 0, (size_t)N_NODES * OUT_F * sizeof(float), 0);
    degree_kernel<<<(N_EDGES + 255) / 256, 256>>>(src, dst);
    gemm_kernel<<<(N_NODES + 127) / 128, 256>>>(feat, weight);

    long long sthreads = (long long)N_EDGES * 32;
    int sblocks = (int)((sthreads + 255) / 256);
    scatter_kernel<<<sblocks, 256>>>(src, dst, ew, out);

    finalize_kernel<<<(N_NODES * (OUT_F / 4) + 255) / 256, 256>>>(out, bias);
}